// round 2
// baseline (speedup 1.0000x reference)
#include <cuda_runtime.h>
#include <cstdint>

#define BATCH   8192
#define IN_DIM  2048
#define HID_DIM 2048
#define K_TOT   4096

#define BM 128
#define BN 32          // per gate; 4 gates fused -> 128 effective N per CTA
#define BK 16
#define ASTR 20        // 16 + pad, 16B-aligned rows, conflict-free A frags
#define BSTR 36        // 32 + pad, 16B-aligned rows

__device__ __forceinline__ uint32_t f2tf32(float f) {
    uint32_t r;
    asm("cvt.rna.tf32.f32 %0, %1;" : "=r"(r) : "f"(f));
    return r;
}

__device__ __forceinline__ float sigf(float z) { return 1.0f / (1.0f + expf(-z)); }

__device__ __forceinline__ void mma_tf32(float c[4],
                                         uint32_t a0, uint32_t a1, uint32_t a2, uint32_t a3,
                                         uint32_t b0, uint32_t b1) {
    asm volatile(
        "mma.sync.aligned.m16n8k8.row.col.f32.tf32.tf32.f32 "
        "{%0,%1,%2,%3}, {%4,%5,%6,%7}, {%8,%9}, {%0,%1,%2,%3};"
        : "+f"(c[0]), "+f"(c[1]), "+f"(c[2]), "+f"(c[3])
        : "r"(a0), "r"(a1), "r"(a2), "r"(a3), "r"(b0), "r"(b1));
}

__global__ __launch_bounds__(256, 2)
void lstm_fused_kernel(const float* __restrict__ x,  const float* __restrict__ hp,
                       const float* __restrict__ cp,
                       const float* __restrict__ Wf, const float* __restrict__ Wi,
                       const float* __restrict__ Wc, const float* __restrict__ Wo,
                       const float* __restrict__ bf, const float* __restrict__ bi,
                       const float* __restrict__ bc, const float* __restrict__ bo,
                       float* __restrict__ out_h, float* __restrict__ out_c)
{
    __shared__ float As[2][BM * ASTR];
    __shared__ float Bs[2][4][BK * BSTR];

    const int tid    = threadIdx.x;
    const int lane   = tid & 31;
    const int wid    = tid >> 5;
    const int warp_m = wid & 3;   // 0..3  (32 rows each)
    const int warp_n = wid >> 2;  // 0..1  (16 cols each)

    const int m0 = blockIdx.y * BM;
    const int n0 = blockIdx.x * BN;

    const float* Wg4[4] = {Wf, Wi, Wc, Wo};

    // A staging: 2048 floats / 256 thr = 2 float4 each
    const int aI0 = tid * 2;
    const int ar0 = aI0 >> 2,        ac0 = (aI0 & 3) << 2;
    const int ar1 = (aI0 + 1) >> 2,  ac1 = ((aI0 + 1) & 3) << 2;
    // B staging: 4 gates x 16 x 32 = 2048 floats = 2 float4 each
    const int bI0 = tid * 2;
    const int bg0 = bI0 >> 7,       bk0 = (bI0 & 127) >> 3,       bj0 = (bI0 & 7) << 2;
    const int bg1 = (bI0 + 1) >> 7, bk1 = ((bI0 + 1) & 127) >> 3, bj1 = ((bI0 + 1) & 7) << 2;

    float acc[4][2][2][4];
    #pragma unroll
    for (int g = 0; g < 4; g++)
        #pragma unroll
        for (int mt = 0; mt < 2; mt++)
            #pragma unroll
            for (int nt = 0; nt < 2; nt++)
                #pragma unroll
                for (int r = 0; r < 4; r++)
                    acc[g][mt][nt][r] = 0.0f;

    float4 ra0, ra1, rb0, rb1;

    auto loadG = [&](int k0) {
        const float* abase = x;
        int kk = k0;
        if (k0 >= IN_DIM) { abase = hp; kk = k0 - IN_DIM; }
        ra0 = *(const float4*)(abase + (size_t)(m0 + ar0) * IN_DIM + kk + ac0);
        ra1 = *(const float4*)(abase + (size_t)(m0 + ar1) * IN_DIM + kk + ac1);
        rb0 = *(const float4*)(Wg4[bg0] + (size_t)(k0 + bk0) * HID_DIM + n0 + bj0);
        rb1 = *(const float4*)(Wg4[bg1] + (size_t)(k0 + bk1) * HID_DIM + n0 + bj1);
    };

    auto cvt4 = [](float4 v) -> float4 {
        float4 r;
        r.x = __uint_as_float(f2tf32(v.x));
        r.y = __uint_as_float(f2tf32(v.y));
        r.z = __uint_as_float(f2tf32(v.z));
        r.w = __uint_as_float(f2tf32(v.w));
        return r;
    };

    auto storeS = [&](int buf) {
        *(float4*)&As[buf][ar0 * ASTR + ac0]       = cvt4(ra0);
        *(float4*)&As[buf][ar1 * ASTR + ac1]       = cvt4(ra1);
        *(float4*)&Bs[buf][bg0][bk0 * BSTR + bj0]  = cvt4(rb0);
        *(float4*)&Bs[buf][bg1][bk1 * BSTR + bj1]  = cvt4(rb1);
    };

    auto compute = [&](int buf) {
        #pragma unroll
        for (int kk = 0; kk < 2; kk++) {
            uint32_t a[2][4];
            #pragma unroll
            for (int mt = 0; mt < 2; mt++) {
                int row = warp_m * 32 + mt * 16 + (lane >> 2);
                int col = kk * 8 + (lane & 3);
                a[mt][0] = __float_as_uint(As[buf][row * ASTR + col]);
                a[mt][1] = __float_as_uint(As[buf][(row + 8) * ASTR + col]);
                a[mt][2] = __float_as_uint(As[buf][row * ASTR + col + 4]);
                a[mt][3] = __float_as_uint(As[buf][(row + 8) * ASTR + col + 4]);
            }
            #pragma unroll
            for (int g = 0; g < 4; g++) {
                #pragma unroll
                for (int nt = 0; nt < 2; nt++) {
                    int coln = warp_n * 16 + nt * 8 + (lane >> 2);
                    int krow = kk * 8 + (lane & 3);
                    uint32_t b0 = __float_as_uint(Bs[buf][g][krow * BSTR + coln]);
                    uint32_t b1 = __float_as_uint(Bs[buf][g][(krow + 4) * BSTR + coln]);
                    #pragma unroll
                    for (int mt = 0; mt < 2; mt++)
                        mma_tf32(acc[g][mt][nt],
                                 a[mt][0], a[mt][1], a[mt][2], a[mt][3], b0, b1);
                }
            }
        }
    };

    // ---- mainloop: double-buffered, LDG prefetch overlapped with MMA ----
    loadG(0);
    storeS(0);
    __syncthreads();

    int buf = 0;
    const int nIter = K_TOT / BK;
    for (int it = 0; it < nIter; it++) {
        const bool has_next = (it + 1) < nIter;
        if (has_next) loadG((it + 1) * BK);
        compute(buf);
        if (has_next) {
            storeS(buf ^ 1);
            __syncthreads();
            buf ^= 1;
        }
    }

    // ---- fused LSTM epilogue ----
    #pragma unroll
    for (int mt = 0; mt < 2; mt++) {
        #pragma unroll
        for (int nt = 0; nt < 2; nt++) {
            int col = n0 + warp_n * 16 + nt * 8 + (lane & 3) * 2;
            float2 bf2 = *(const float2*)(bf + col);
            float2 bi2 = *(const float2*)(bi + col);
            float2 bc2 = *(const float2*)(bc + col);
            float2 bo2 = *(const float2*)(bo + col);
            #pragma unroll
            for (int half = 0; half < 2; half++) {
                int m = m0 + warp_m * 32 + mt * 16 + (lane >> 2) + half * 8;
                size_t base = (size_t)m * HID_DIM + col;
                float2 cpv = *(const float2*)(cp + base);
                int i0 = half * 2;
                float zf0 = acc[0][mt][nt][i0]     + bf2.x;
                float zf1 = acc[0][mt][nt][i0 + 1] + bf2.y;
                float zi0 = acc[1][mt][nt][i0]     + bi2.x;
                float zi1 = acc[1][mt][nt][i0 + 1] + bi2.y;
                float zc0 = acc[2][mt][nt][i0]     + bc2.x;
                float zc1 = acc[2][mt][nt][i0 + 1] + bc2.y;
                float zo0 = acc[3][mt][nt][i0]     + bo2.x;
                float zo1 = acc[3][mt][nt][i0 + 1] + bo2.y;

                float f0 = sigf(zf0),  f1 = sigf(zf1);
                float i0v = sigf(zi0), i1v = sigf(zi1);
                float g0 = tanhf(zc0), g1 = tanhf(zc1);
                float o0 = sigf(zo0),  o1 = sigf(zo1);

                float cn0 = cpv.x * f0 + i0v * g0;
                float cn1 = cpv.y * f1 + i1v * g1;
                float h0 = o0 * tanhf(cn0);
                float h1 = o1 * tanhf(cn1);

                *(float2*)(out_h + base) = make_float2(h0, h1);
                *(float2*)(out_c + base) = make_float2(cn0, cn1);
            }
        }
    }
}

extern "C" void kernel_launch(void* const* d_in, const int* in_sizes, int n_in,
                              void* d_out, int out_size) {
    // metadata order: x, h_prev, c_prev, embedding_vec, Wf, Wi, Wc, Wo, bf, bi, bc, bo
    const float* x  = (const float*)d_in[0];
    const float* hp = (const float*)d_in[1];
    const float* cp = (const float*)d_in[2];
    const float* Wf = (const float*)d_in[4];
    const float* Wi = (const float*)d_in[5];
    const float* Wc = (const float*)d_in[6];
    const float* Wo = (const float*)d_in[7];
    const float* bf = (const float*)d_in[8];
    const float* bi = (const float*)d_in[9];
    const float* bc = (const float*)d_in[10];
    const float* bo = (const float*)d_in[11];

    float* out_h = (float*)d_out;                              // h_t first
    float* out_c = out_h + (size_t)BATCH * HID_DIM;            // then c_t

    dim3 grid(HID_DIM / BN, BATCH / BM);   // 64 x 64
    lstm_fused_kernel<<<grid, 256>>>(x, hp, cp, Wf, Wi, Wc, Wo,
                                     bf, bi, bc, bo, out_h, out_c);
}

// round 8
// speedup vs baseline: 1.2457x; 1.2457x over previous
#include <cuda_runtime.h>
#include <cstdint>
#include <cstddef>

#define BATCH   8192
#define HID     2048
#define KTOT    4096
#define BM      128
#define BNG     64            // per-gate N cols per CTA (4 gates -> 256 cols total)
#define BK      16
#define ASTR    20            // A row stride (16 + 4 pad) -> conflict-free frag reads
#define BSTR    264           // B row stride (256 + 8 pad) -> conflict-free frag reads
#define NITER   (KTOT / BK)   // 256

#define A_FLOATS (BM * ASTR)          // 2560
#define B_FLOATS (BK * BSTR)          // 4224
#define SMEM_BYTES ((2 * A_FLOATS + 2 * B_FLOATS) * 4)   // 54272

__device__ __forceinline__ uint32_t f2tf32(float f) {
    uint32_t r;
    asm("cvt.rna.tf32.f32 %0, %1;" : "=r"(r) : "f"(f));
    return r;
}

__device__ __forceinline__ float4 cvt4(float4 v) {
    float4 r;
    r.x = __uint_as_float(f2tf32(v.x));
    r.y = __uint_as_float(f2tf32(v.y));
    r.z = __uint_as_float(f2tf32(v.z));
    r.w = __uint_as_float(f2tf32(v.w));
    return r;
}

__device__ __forceinline__ float sigf(float z) { return 1.0f / (1.0f + expf(-z)); }

__device__ __forceinline__ void mma_tf32(float c[4],
                                         uint32_t a0, uint32_t a1, uint32_t a2, uint32_t a3,
                                         uint32_t b0, uint32_t b1) {
    asm volatile(
        "mma.sync.aligned.m16n8k8.row.col.f32.tf32.tf32.f32 "
        "{%0,%1,%2,%3}, {%4,%5,%6,%7}, {%8,%9}, {%0,%1,%2,%3};"
        : "+f"(c[0]), "+f"(c[1]), "+f"(c[2]), "+f"(c[3])
        : "r"(a0), "r"(a1), "r"(a2), "r"(a3), "r"(b0), "r"(b1));
}

__global__ __launch_bounds__(256, 1)
void lstm_big_kernel(const float* __restrict__ x,  const float* __restrict__ hp,
                     const float* __restrict__ cp,
                     const float* __restrict__ Wf, const float* __restrict__ Wi,
                     const float* __restrict__ Wc, const float* __restrict__ Wo,
                     const float* __restrict__ bf, const float* __restrict__ bi,
                     const float* __restrict__ bc, const float* __restrict__ bo,
                     float* __restrict__ out_h, float* __restrict__ out_c)
{
    extern __shared__ float smem[];
    float* As = smem;                       // 2 bufs x 2560
    float* Bs = smem + 2 * A_FLOATS;        // 2 bufs x 4224

    const int tid    = threadIdx.x;
    const int lane   = tid & 31;
    const int wid    = tid >> 5;
    const int warp_m = wid & 1;   // 0..1 : 64 rows each
    const int warp_n = wid >> 1;  // 0..3 : 16 cols per gate each (gate-interleaved)

    const int m0 = blockIdx.x * BM;   // m fast-varying -> W stays hot in L2
    const int n0 = blockIdx.y * BNG;

    const float* Wg4[4] = {Wf, Wi, Wc, Wo};

    // ---- staging index precompute ----
    // A: 2048 floats/iter = 2 float4 per thread.  fl = tid + 256*j
    // row = fl>>2 (0..127), c4 = (fl&3)*4  -> STS conflict-free-ish, LDG 32B/row pairs
    // B: 4096 floats/iter = 4 float4 per thread.  fl4 = tid + 256*j
    // g = fl4>>8, k = (fl4>>4)&15, n4 = fl4&15 -> LDG 256B contiguous per 16 lanes,
    // STS phases conflict-free with BSTR=264.

    float acc[4][4][2][4];   // [gate][mt][nt][reg]
    #pragma unroll
    for (int g = 0; g < 4; g++)
        #pragma unroll
        for (int mt = 0; mt < 4; mt++)
            #pragma unroll
            for (int nt = 0; nt < 2; nt++)
                #pragma unroll
                for (int r = 0; r < 4; r++)
                    acc[g][mt][nt][r] = 0.0f;

    float4 ra[2], rb[4];

    auto loadG = [&](int k0) {
        const float* abase = x;
        int kk = k0;
        if (k0 >= 2048) { abase = hp; kk = k0 - 2048; }
        #pragma unroll
        for (int j = 0; j < 2; j++) {
            int fl = tid + 256 * j;
            int row = fl >> 2, c4 = (fl & 3) << 2;
            ra[j] = *(const float4*)(abase + (size_t)(m0 + row) * 2048 + kk + c4);
        }
        #pragma unroll
        for (int j = 0; j < 4; j++) {
            int fl4 = tid + 256 * j;
            int g = fl4 >> 8, bk = (fl4 >> 4) & 15, n4 = fl4 & 15;
            rb[j] = *(const float4*)(Wg4[g] + (size_t)(k0 + bk) * HID + n0 + n4 * 4);
        }
    };

    auto storeS = [&](int buf) {
        float* Ab = As + buf * A_FLOATS;
        float* Bb = Bs + buf * B_FLOATS;
        #pragma unroll
        for (int j = 0; j < 2; j++) {
            int fl = tid + 256 * j;
            int row = fl >> 2, c4 = (fl & 3) << 2;
            *(float4*)&Ab[row * ASTR + c4] = cvt4(ra[j]);
        }
        #pragma unroll
        for (int j = 0; j < 4; j++) {
            int fl4 = tid + 256 * j;
            int g = fl4 >> 8, bk = (fl4 >> 4) & 15, n4 = fl4 & 15;
            *(float4*)&Bb[bk * BSTR + g * 64 + n4 * 4] = cvt4(rb[j]);
        }
    };

    auto compute = [&](int buf) {
        const float* Ab = As + buf * A_FLOATS;
        const float* Bb = Bs + buf * B_FLOATS;
        #pragma unroll
        for (int kk = 0; kk < 2; kk++) {
            const int kc = kk * 8 + (lane & 3);
            uint32_t a[4][4];
            #pragma unroll
            for (int mt = 0; mt < 4; mt++) {
                int row = warp_m * 64 + mt * 16 + (lane >> 2);
                a[mt][0] = __float_as_uint(Ab[row * ASTR + kc]);
                a[mt][1] = __float_as_uint(Ab[(row + 8) * ASTR + kc]);
                a[mt][2] = __float_as_uint(Ab[row * ASTR + kc + 4]);
                a[mt][3] = __float_as_uint(Ab[(row + 8) * ASTR + kc + 4]);
            }
            #pragma unroll
            for (int g = 0; g < 4; g++) {
                #pragma unroll
                for (int nt = 0; nt < 2; nt++) {
                    int coln = g * 64 + warp_n * 16 + nt * 8 + (lane >> 2);
                    uint32_t b0 = __float_as_uint(Bb[kc * BSTR + coln]);
                    uint32_t b1 = __float_as_uint(Bb[(kc + 4 - (lane & 3) + (lane & 3)) * BSTR + coln]);
                    // b1 row = kc+4 (written explicitly to keep compiler from CSE confusion)
                    #pragma unroll
                    for (int mt = 0; mt < 4; mt++)
                        mma_tf32(acc[g][mt][nt],
                                 a[mt][0], a[mt][1], a[mt][2], a[mt][3], b0, b1);
                }
            }
        }
    };

    // ---- mainloop: double-buffered ----
    loadG(0);
    storeS(0);
    __syncthreads();

    int buf = 0;
    for (int it = 0; it < NITER; it++) {
        const bool has_next = (it + 1) < NITER;
        if (has_next) loadG((it + 1) * BK);
        compute(buf);
        if (has_next) {
            storeS(buf ^ 1);
            __syncthreads();
            buf ^= 1;
        }
    }

    // ---- fused LSTM epilogue ----
    #pragma unroll
    for (int nt = 0; nt < 2; nt++) {
        const int col = n0 + warp_n * 16 + nt * 8 + (lane & 3) * 2;
        float2 bf2 = *(const float2*)(bf + col);
        float2 bi2 = *(const float2*)(bi + col);
        float2 bc2 = *(const float2*)(bc + col);
        float2 bo2 = *(const float2*)(bo + col);
        #pragma unroll
        for (int mt = 0; mt < 4; mt++) {
            #pragma unroll
            for (int half = 0; half < 2; half++) {
                const int m = m0 + warp_m * 64 + mt * 16 + (lane >> 2) + half * 8;
                const size_t base = (size_t)m * HID + col;
                float2 cpv = *(const float2*)(cp + base);
                const int i0 = half * 2;
                float zf0 = acc[0][mt][nt][i0]     + bf2.x;
                float zf1 = acc[0][mt][nt][i0 + 1] + bf2.y;
                float zi0 = acc[1][mt][nt][i0]     + bi2.x;
                float zi1 = acc[1][mt][nt][i0 + 1] + bi2.y;
                float zc0 = acc[2][mt][nt][i0]     + bc2.x;
                float zc1 = acc[2][mt][nt][i0 + 1] + bc2.y;
                float zo0 = acc[3][mt][nt][i0]     + bo2.x;
                float zo1 = acc[3][mt][nt][i0 + 1] + bo2.y;

                float f0 = sigf(zf0),   f1 = sigf(zf1);
                float iv0 = sigf(zi0),  iv1 = sigf(zi1);
                float g0 = tanhf(zc0),  g1 = tanhf(zc1);
                float o0 = sigf(zo0),   o1 = sigf(zo1);

                float cn0 = cpv.x * f0 + iv0 * g0;
                float cn1 = cpv.y * f1 + iv1 * g1;
                float h0 = o0 * tanhf(cn0);
                float h1 = o1 * tanhf(cn1);

                *(float2*)(out_h + base) = make_float2(h0, h1);
                *(float2*)(out_c + base) = make_float2(cn0, cn1);
            }
        }
    }
}

extern "C" void kernel_launch(void* const* d_in, const int* in_sizes, int n_in,
                              void* d_out, int out_size) {
    // metadata order: x, h_prev, c_prev, embedding_vec, Wf, Wi, Wc, Wo, bf, bi, bc, bo
    const float* x  = (const float*)d_in[0];
    const float* hp = (const float*)d_in[1];
    const float* cp = (const float*)d_in[2];
    const float* Wf = (const float*)d_in[4];
    const float* Wi = (const float*)d_in[5];
    const float* Wc = (const float*)d_in[6];
    const float* Wo = (const float*)d_in[7];
    const float* bf = (const float*)d_in[8];
    const float* bi = (const float*)d_in[9];
    const float* bc = (const float*)d_in[10];
    const float* bo = (const float*)d_in[11];

    float* out_h = (float*)d_out;
    float* out_c = out_h + (size_t)BATCH * HID;

    cudaFuncSetAttribute(lstm_big_kernel,
                         cudaFuncAttributeMaxDynamicSharedMemorySize, SMEM_BYTES);

    dim3 grid(BATCH / BM, HID / BNG);   // (64, 32); m fast-varying
    lstm_big_kernel<<<grid, 256, SMEM_BYTES>>>(x, hp, cp, Wf, Wi, Wc, Wo,
                                               bf, bi, bc, bo, out_h, out_c);
}

// round 10
// speedup vs baseline: 1.6491x; 1.3238x over previous
#include <cuda_runtime.h>
#include <cstdint>
#include <cstddef>

#define BATCH   8192
#define HID     2048
#define KTOT    4096
#define BM      128
#define BNG     64              // per-gate cols per CTA (4 gates -> 256)
#define BK      16
#define NKB     (KTOT / BK)     // 256 k-blocks
#define A_BLK   2048            // floats per packed A block (128x16)
#define B_BLK   4096            // floats per packed B block (16x256)
#define NSTAGE  4
#define STG_FLT (A_BLK + B_BLK) // 6144 floats = 24KB
#define SMEM_BYTES (NSTAGE * STG_FLT * 4)   // 96KB

// 256MB packed tf32 scratch (device-global: the sanctioned no-alloc workaround)
__device__ __align__(16) float ABUF[(size_t)BATCH * KTOT];      // 64 mblk x 256 kb x 2048
__device__ __align__(16) float WBUF[(size_t)KTOT * 4 * HID];    // 32 nblk x 256 kb x 4096

__device__ __forceinline__ uint32_t s2u(const void* p) {
    uint32_t a;
    asm("{.reg .u64 t; cvta.to.shared.u64 t, %1; cvt.u32.u64 %0, t;}" : "=r"(a) : "l"(p));
    return a;
}

__device__ __forceinline__ float f2tf32f(float f) {
    uint32_t r;
    asm("cvt.rna.tf32.f32 %0, %1;" : "=r"(r) : "f"(f));
    return __uint_as_float(r);
}

__device__ __forceinline__ void cpa16(uint32_t dst, const float4* src) {
    asm volatile("cp.async.cg.shared.global [%0], [%1], 16;" :: "r"(dst), "l"(src));
}

__device__ __forceinline__ float sigf(float z) { return 1.0f / (1.0f + expf(-z)); }

__device__ __forceinline__ void mma_tf32(float c[4],
                                         uint32_t a0, uint32_t a1, uint32_t a2, uint32_t a3,
                                         uint32_t b0, uint32_t b1) {
    asm volatile(
        "mma.sync.aligned.m16n8k8.row.col.f32.tf32.tf32.f32 "
        "{%0,%1,%2,%3}, {%4,%5,%6,%7}, {%8,%9}, {%0,%1,%2,%3};"
        : "+f"(c[0]), "+f"(c[1]), "+f"(c[2]), "+f"(c[3])
        : "r"(a0), "r"(a1), "r"(a2), "r"(a3), "r"(b0), "r"(b1));
}

// ---------------- prepass: pack A (x||h) into fragment order ----------------
// PA[kk][wm][mt][lane][w] : row = wm*64+mt*16+(l>>2)+(w&1)*8 ; k = kk*8+(l&3)+(w>>1)*4
__global__ __launch_bounds__(256)
void packA_kernel(const float* __restrict__ x, const float* __restrict__ hp) {
    __shared__ float st[A_BLK];
    const int mblk = blockIdx.x, kb = blockIdx.y, tid = threadIdx.x;
    #pragma unroll
    for (int j = 0; j < 8; j++) {
        int fl = tid + 256 * j;
        int row = fl >> 4, k = fl & 15;
        int gk = kb * 16 + k;
        const float* src = (gk < 2048) ? x : hp;
        int kk2 = (gk < 2048) ? gk : gk - 2048;
        st[fl] = src[(size_t)(mblk * 128 + row) * 2048 + kk2];
    }
    __syncthreads();
    float* dst = ABUF + (size_t)(mblk * NKB + kb) * A_BLK;
    #pragma unroll
    for (int j = 0; j < 8; j++) {
        int d = tid + 256 * j;
        int w = d & 3, l = (d >> 2) & 31, mt = (d >> 7) & 3, wm = (d >> 9) & 1, kk = (d >> 10) & 1;
        int row = wm * 64 + mt * 16 + (l >> 2) + (w & 1) * 8;
        int k   = kk * 8 + (l & 3) + (w >> 1) * 4;
        dst[d] = f2tf32f(st[row * 16 + k]);
    }
}

// ---------------- prepass: pack W (4 gates) into fragment order ----------------
// PB[kk][wn][g][nt][lane][w] : k = kk*8+(l&3)+w*4 ; col = wn*16+nt*8+(l>>2)
__global__ __launch_bounds__(256)
void packB_kernel(const float* __restrict__ Wf, const float* __restrict__ Wi,
                  const float* __restrict__ Wc, const float* __restrict__ Wo) {
    __shared__ float st[B_BLK];   // [g][16][64]
    const int nblk = blockIdx.x, kb = blockIdx.y, tid = threadIdx.x;
    const float* Wg[4] = {Wf, Wi, Wc, Wo};
    #pragma unroll
    for (int g = 0; g < 4; g++) {
        #pragma unroll
        for (int j = 0; j < 4; j++) {
            int fl = tid + 256 * j;
            int krow = fl >> 6, col = fl & 63;
            st[g * 1024 + fl] = Wg[g][(size_t)(kb * 16 + krow) * HID + nblk * 64 + col];
        }
    }
    __syncthreads();
    float* dst = WBUF + (size_t)(nblk * NKB + kb) * B_BLK;
    #pragma unroll
    for (int j = 0; j < 16; j++) {
        int d = tid + 256 * j;
        int w = d & 1, l = (d >> 1) & 31, nt = (d >> 6) & 1, g = (d >> 7) & 3,
            wn = (d >> 9) & 3, kk = (d >> 11) & 1;
        int k   = kk * 8 + (l & 3) + w * 4;
        int col = wn * 16 + nt * 8 + (l >> 2);
        dst[d] = f2tf32f(st[g * 1024 + k * 64 + col]);
    }
}

// ---------------- main GEMM + fused LSTM ----------------
__global__ __launch_bounds__(256, 1)
void lstm_mm_kernel(const float* __restrict__ cp,
                    const float* __restrict__ bf, const float* __restrict__ bi,
                    const float* __restrict__ bc, const float* __restrict__ bo,
                    float* __restrict__ out_h, float* __restrict__ out_c)
{
    extern __shared__ float sm[];
    const int tid    = threadIdx.x;
    const int lane   = tid & 31;
    const int wid    = tid >> 5;
    const int warp_m = wid & 1;   // 64 rows
    const int warp_n = wid >> 1;  // 16 cols per gate

    const int mblk = blockIdx.x;  // m fast-varying -> W hot in L2
    const int nblk = blockIdx.y;

    const float4* Ag = (const float4*)(ABUF + (size_t)mblk * NKB * A_BLK);
    const float4* Bg = (const float4*)(WBUF + (size_t)nblk * NKB * B_BLK);
    const uint32_t smb = s2u(sm);

    float acc[4][4][2][4];
    #pragma unroll
    for (int g = 0; g < 4; g++)
        #pragma unroll
        for (int mt = 0; mt < 4; mt++)
            #pragma unroll
            for (int nt = 0; nt < 2; nt++)
                #pragma unroll
                for (int r = 0; r < 4; r++)
                    acc[g][mt][nt][r] = 0.0f;

    auto issue = [&](int kb) {
        const int s = kb & (NSTAGE - 1);
        const uint32_t da = smb + (uint32_t)(s * STG_FLT * 4) + (uint32_t)tid * 16;
        const float4* srcA = Ag + (size_t)kb * (A_BLK / 4) + tid;
        cpa16(da, srcA);
        cpa16(da + 256 * 16, srcA + 256);
        const uint32_t db = da + A_BLK * 4;
        const float4* srcB = Bg + (size_t)kb * (B_BLK / 4) + tid;
        #pragma unroll
        for (int j = 0; j < 4; j++)
            cpa16(db + (uint32_t)(j * 256 * 16), srcB + j * 256);
    };

    auto compute = [&](int s) {
        const float* Ab = sm + s * STG_FLT;
        const float* Bb = Ab + A_BLK;
        #pragma unroll
        for (int kk = 0; kk < 2; kk++) {
            float4 af[4];
            #pragma unroll
            for (int mt = 0; mt < 4; mt++)
                af[mt] = *(const float4*)&Ab[(((kk * 2 + warp_m) * 4 + mt) * 32 + lane) * 4];
            #pragma unroll
            for (int g = 0; g < 4; g++) {
                #pragma unroll
                for (int nt = 0; nt < 2; nt++) {
                    float2 b2 = *(const float2*)
                        &Bb[(((((kk * 4 + warp_n) * 4 + g) * 2 + nt)) * 32 + lane) * 2];
                    const uint32_t b0 = __float_as_uint(b2.x);
                    const uint32_t b1 = __float_as_uint(b2.y);
                    #pragma unroll
                    for (int mt = 0; mt < 4; mt++)
                        mma_tf32(acc[g][mt][nt],
                                 __float_as_uint(af[mt].x), __float_as_uint(af[mt].y),
                                 __float_as_uint(af[mt].z), __float_as_uint(af[mt].w),
                                 b0, b1);
                }
            }
        }
    };

    // prologue: 3 stages in flight
    #pragma unroll
    for (int kb = 0; kb < NSTAGE - 1; kb++) {
        issue(kb);
        asm volatile("cp.async.commit_group;");
    }

    for (int kb = 0; kb < NKB; kb++) {
        asm volatile("cp.async.wait_group %0;" :: "n"(NSTAGE - 2));
        __syncthreads();
        if (kb + NSTAGE - 1 < NKB) issue(kb + NSTAGE - 1);
        asm volatile("cp.async.commit_group;");
        compute(kb & (NSTAGE - 1));
    }

    // ---- fused LSTM epilogue ----
    const int m0 = mblk * BM;
    const int n0 = nblk * BNG;
    #pragma unroll
    for (int nt = 0; nt < 2; nt++) {
        const int col = n0 + warp_n * 16 + nt * 8 + (lane & 3) * 2;
        float2 bf2 = *(const float2*)(bf + col);
        float2 bi2 = *(const float2*)(bi + col);
        float2 bc2 = *(const float2*)(bc + col);
        float2 bo2 = *(const float2*)(bo + col);
        #pragma unroll
        for (int mt = 0; mt < 4; mt++) {
            #pragma unroll
            for (int half = 0; half < 2; half++) {
                const int m = m0 + warp_m * 64 + mt * 16 + (lane >> 2) + half * 8;
                const size_t base = (size_t)m * HID + col;
                float2 cpv = *(const float2*)(cp + base);
                const int i0 = half * 2;
                float zf0 = acc[0][mt][nt][i0]     + bf2.x;
                float zf1 = acc[0][mt][nt][i0 + 1] + bf2.y;
                float zi0 = acc[1][mt][nt][i0]     + bi2.x;
                float zi1 = acc[1][mt][nt][i0 + 1] + bi2.y;
                float zc0 = acc[2][mt][nt][i0]     + bc2.x;
                float zc1 = acc[2][mt][nt][i0 + 1] + bc2.y;
                float zo0 = acc[3][mt][nt][i0]     + bo2.x;
                float zo1 = acc[3][mt][nt][i0 + 1] + bo2.y;

                float f0 = sigf(zf0),   f1 = sigf(zf1);
                float iv0 = sigf(zi0),  iv1 = sigf(zi1);
                float g0 = tanhf(zc0),  g1 = tanhf(zc1);
                float o0 = sigf(zo0),   o1 = sigf(zo1);

                float cn0 = cpv.x * f0 + iv0 * g0;
                float cn1 = cpv.y * f1 + iv1 * g1;
                float h0 = o0 * tanhf(cn0);
                float h1 = o1 * tanhf(cn1);

                *(float2*)(out_h + base) = make_float2(h0, h1);
                *(float2*)(out_c + base) = make_float2(cn0, cn1);
            }
        }
    }
}

extern "C" void kernel_launch(void* const* d_in, const int* in_sizes, int n_in,
                              void* d_out, int out_size) {
    // order: x, h_prev, c_prev, embedding_vec, Wf, Wi, Wc, Wo, bf, bi, bc, bo
    const float* x  = (const float*)d_in[0];
    const float* hp = (const float*)d_in[1];
    const float* cp = (const float*)d_in[2];
    const float* Wf = (const float*)d_in[4];
    const float* Wi = (const float*)d_in[5];
    const float* Wc = (const float*)d_in[6];
    const float* Wo = (const float*)d_in[7];
    const float* bf = (const float*)d_in[8];
    const float* bi = (const float*)d_in[9];
    const float* bc = (const float*)d_in[10];
    const float* bo = (const float*)d_in[11];

    float* out_h = (float*)d_out;
    float* out_c = out_h + (size_t)BATCH * HID;

    packA_kernel<<<dim3(BATCH / BM, NKB), 256>>>(x, hp);
    packB_kernel<<<dim3(HID / BNG, NKB), 256>>>(Wf, Wi, Wc, Wo);

    cudaFuncSetAttribute(lstm_mm_kernel,
                         cudaFuncAttributeMaxDynamicSharedMemorySize, SMEM_BYTES);
    dim3 grid(BATCH / BM, HID / BNG);   // (64, 32)
    lstm_mm_kernel<<<grid, 256, SMEM_BYTES>>>(cp, bf, bi, bc, bo, out_h, out_c);
}

// round 12
// speedup vs baseline: 1.7449x; 1.0581x over previous
#include <cuda_runtime.h>
#include <cstdint>
#include <cstddef>

#define BATCH   8192
#define HID     2048
#define KTOT    4096
#define BM      128
#define BNG     64              // per-gate cols per CTA (4 gates -> 256)
#define NKB     (KTOT / 16)     // 256 packed 16-k units
#define NKB32   (KTOT / 32)     // 128 mainloop stages
#define A_BLK   2048            // floats per packed A unit (128x16)
#define B_BLK   4096            // floats per packed B unit (16x256)
#define UNIT    (A_BLK + B_BLK) // 6144 floats = 24KB
#define NSTAGE  3
#define STG_FLT (2 * UNIT)      // 48KB per stage (two 16-k units)
#define SMEM_BYTES (NSTAGE * STG_FLT * 4)   // 144KB

__device__ __align__(16) float ABUF[(size_t)BATCH * KTOT];
__device__ __align__(16) float WBUF[(size_t)KTOT * 4 * HID];

__device__ __forceinline__ uint32_t s2u(const void* p) {
    uint32_t a;
    asm("{.reg .u64 t; cvta.to.shared.u64 t, %1; cvt.u32.u64 %0, t;}" : "=r"(a) : "l"(p));
    return a;
}

__device__ __forceinline__ float f2tf32f(float f) {
    uint32_t r;
    asm("cvt.rna.tf32.f32 %0, %1;" : "=r"(r) : "f"(f));
    return __uint_as_float(r);
}

__device__ __forceinline__ void cpa16(uint32_t dst, const float4* src) {
    asm volatile("cp.async.cg.shared.global [%0], [%1], 16;" :: "r"(dst), "l"(src));
}

__device__ __forceinline__ float sigf(float z) { return 1.0f / (1.0f + expf(-z)); }

__device__ __forceinline__ void mma_tf32(float c[4],
                                         uint32_t a0, uint32_t a1, uint32_t a2, uint32_t a3,
                                         uint32_t b0, uint32_t b1) {
    asm volatile(
        "mma.sync.aligned.m16n8k8.row.col.f32.tf32.tf32.f32 "
        "{%0,%1,%2,%3}, {%4,%5,%6,%7}, {%8,%9}, {%0,%1,%2,%3};"
        : "+f"(c[0]), "+f"(c[1]), "+f"(c[2]), "+f"(c[3])
        : "r"(a0), "r"(a1), "r"(a2), "r"(a3), "r"(b0), "r"(b1));
}

// ---------------- prepass: pack A (x||h) into fragment order ----------------
__global__ __launch_bounds__(256)
void packA_kernel(const float* __restrict__ x, const float* __restrict__ hp) {
    __shared__ float st[A_BLK];
    const int mblk = blockIdx.x, kb = blockIdx.y, tid = threadIdx.x;
    #pragma unroll
    for (int j = 0; j < 8; j++) {
        int fl = tid + 256 * j;
        int row = fl >> 4, k = fl & 15;
        int gk = kb * 16 + k;
        const float* src = (gk < 2048) ? x : hp;
        int kk2 = (gk < 2048) ? gk : gk - 2048;
        st[fl] = src[(size_t)(mblk * 128 + row) * 2048 + kk2];
    }
    __syncthreads();
    float* dst = ABUF + (size_t)(mblk * NKB + kb) * A_BLK;
    #pragma unroll
    for (int j = 0; j < 8; j++) {
        int d = tid + 256 * j;
        int w = d & 3, l = (d >> 2) & 31, mt = (d >> 7) & 3, wm = (d >> 9) & 1, kk = (d >> 10) & 1;
        int row = wm * 64 + mt * 16 + (l >> 2) + (w & 1) * 8;
        int k   = kk * 8 + (l & 3) + (w >> 1) * 4;
        dst[d] = f2tf32f(st[row * 16 + k]);
    }
}

// ---------------- prepass: pack W (4 gates) into fragment order ----------------
__global__ __launch_bounds__(256)
void packB_kernel(const float* __restrict__ Wf, const float* __restrict__ Wi,
                  const float* __restrict__ Wc, const float* __restrict__ Wo) {
    __shared__ float st[B_BLK];   // [g][16][64]
    const int nblk = blockIdx.x, kb = blockIdx.y, tid = threadIdx.x;
    const float* Wg[4] = {Wf, Wi, Wc, Wo};
    #pragma unroll
    for (int g = 0; g < 4; g++) {
        #pragma unroll
        for (int j = 0; j < 4; j++) {
            int fl = tid + 256 * j;
            int krow = fl >> 6, col = fl & 63;
            st[g * 1024 + fl] = Wg[g][(size_t)(kb * 16 + krow) * HID + nblk * 64 + col];
        }
    }
    __syncthreads();
    float* dst = WBUF + (size_t)(nblk * NKB + kb) * B_BLK;
    #pragma unroll
    for (int j = 0; j < 16; j++) {
        int d = tid + 256 * j;
        int w = d & 1, l = (d >> 1) & 31, nt = (d >> 6) & 1, g = (d >> 7) & 3,
            wn = (d >> 9) & 3, kk = (d >> 11) & 1;
        int k   = kk * 8 + (l & 3) + w * 4;
        int col = wn * 16 + nt * 8 + (l >> 2);
        dst[d] = f2tf32f(st[g * 1024 + k * 64 + col]);
    }
}

// ---------------- main GEMM + fused LSTM ----------------
__global__ __launch_bounds__(256, 1)
void lstm_mm_kernel(const float* __restrict__ cp,
                    const float* __restrict__ bf, const float* __restrict__ bi,
                    const float* __restrict__ bc, const float* __restrict__ bo,
                    float* __restrict__ out_h, float* __restrict__ out_c)
{
    extern __shared__ float sm[];
    const int tid    = threadIdx.x;
    const int lane   = tid & 31;
    const int wid    = tid >> 5;
    const int warp_m = wid & 1;   // 64 rows
    const int warp_n = wid >> 1;  // 16 cols per gate

    const int mblk = blockIdx.x;
    const int nblk = blockIdx.y;

    const float4* Ag = (const float4*)(ABUF + (size_t)mblk * NKB * A_BLK);
    const float4* Bg = (const float4*)(WBUF + (size_t)nblk * NKB * B_BLK);
    const uint32_t smb = s2u(sm);

    float acc[4][4][2][4];
    #pragma unroll
    for (int g = 0; g < 4; g++)
        #pragma unroll
        for (int mt = 0; mt < 4; mt++)
            #pragma unroll
            for (int nt = 0; nt < 2; nt++)
                #pragma unroll
                for (int r = 0; r < 4; r++)
                    acc[g][mt][nt][r] = 0.0f;

    // issue one 32-k stage = two consecutive 16-k packed units
    auto issue = [&](int kb32) {
        const int s = kb32 % NSTAGE;
        #pragma unroll
        for (int u = 0; u < 2; u++) {
            const int kb16 = kb32 * 2 + u;
            const uint32_t da = smb + (uint32_t)((s * STG_FLT + u * UNIT) * 4)
                                + (uint32_t)tid * 16;
            const float4* srcA = Ag + (size_t)kb16 * (A_BLK / 4) + tid;
            cpa16(da, srcA);
            cpa16(da + 256 * 16, srcA + 256);
            const uint32_t db = da + A_BLK * 4;
            const float4* srcB = Bg + (size_t)kb16 * (B_BLK / 4) + tid;
            #pragma unroll
            for (int j = 0; j < 4; j++)
                cpa16(db + (uint32_t)(j * 256 * 16), srcB + j * 256);
        }
    };

    auto ldfrag = [&](const float* stage, int sl, float4 af[4], float2 bfr[8]) {
        const float* Ab = stage + (sl >> 1) * UNIT;
        const float* Bb = Ab + A_BLK;
        const int kk = sl & 1;
        #pragma unroll
        for (int mt = 0; mt < 4; mt++)
            af[mt] = *(const float4*)&Ab[(((kk * 2 + warp_m) * 4 + mt) * 32 + lane) * 4];
        #pragma unroll
        for (int g = 0; g < 4; g++)
            #pragma unroll
            for (int nt = 0; nt < 2; nt++)
                bfr[g * 2 + nt] = *(const float2*)
                    &Bb[(((((kk * 4 + warp_n) * 4 + g) * 2 + nt)) * 32 + lane) * 2];
    };

    auto domma = [&](const float4 af[4], const float2 bfr[8]) {
        #pragma unroll
        for (int g = 0; g < 4; g++) {
            #pragma unroll
            for (int nt = 0; nt < 2; nt++) {
                const uint32_t b0 = __float_as_uint(bfr[g * 2 + nt].x);
                const uint32_t b1 = __float_as_uint(bfr[g * 2 + nt].y);
                #pragma unroll
                for (int mt = 0; mt < 4; mt++)
                    mma_tf32(acc[g][mt][nt],
                             __float_as_uint(af[mt].x), __float_as_uint(af[mt].y),
                             __float_as_uint(af[mt].z), __float_as_uint(af[mt].w),
                             b0, b1);
            }
        }
    };

    // prologue: 2 stages in flight
    issue(0);
    asm volatile("cp.async.commit_group;");
    issue(1);
    asm volatile("cp.async.commit_group;");

    float4 afr[2][4];
    float2 bfr2[2][8];

    for (int kb = 0; kb < NKB32; kb++) {
        asm volatile("cp.async.wait_group %0;" :: "n"(1));
        __syncthreads();
        if (kb + 2 < NKB32) issue(kb + 2);
        asm volatile("cp.async.commit_group;");

        const float* stage = sm + (kb % NSTAGE) * STG_FLT;
        ldfrag(stage, 0, afr[0], bfr2[0]);
        int cur = 0;
        #pragma unroll
        for (int sl = 0; sl < 4; sl++) {
            const int nxt = cur ^ 1;
            if (sl < 3) ldfrag(stage, sl + 1, afr[nxt], bfr2[nxt]);
            domma(afr[cur], bfr2[cur]);
            cur = nxt;
        }
    }

    // ---- fused LSTM epilogue ----
    const int m0 = mblk * BM;
    const int n0 = nblk * BNG;
    #pragma unroll
    for (int nt = 0; nt < 2; nt++) {
        const int col = n0 + warp_n * 16 + nt * 8 + (lane & 3) * 2;
        float2 bf2 = *(const float2*)(bf + col);
        float2 bi2 = *(const float2*)(bi + col);
        float2 bc2 = *(const float2*)(bc + col);
        float2 bo2 = *(const float2*)(bo + col);
        #pragma unroll
        for (int mt = 0; mt < 4; mt++) {
            #pragma unroll
            for (int half = 0; half < 2; half++) {
                const int m = m0 + warp_m * 64 + mt * 16 + (lane >> 2) + half * 8;
                const size_t base = (size_t)m * HID + col;
                float2 cpv = *(const float2*)(cp + base);
                const int i0 = half * 2;
                float zf0 = acc[0][mt][nt][i0]     + bf2.x;
                float zf1 = acc[0][mt][nt][i0 + 1] + bf2.y;
                float zi0 = acc[1][mt][nt][i0]     + bi2.x;
                float zi1 = acc[1][mt][nt][i0 + 1] + bi2.y;
                float zc0 = acc[2][mt][nt][i0]     + bc2.x;
                float zc1 = acc[2][mt][nt][i0 + 1] + bc2.y;
                float zo0 = acc[3][mt][nt][i0]     + bo2.x;
                float zo1 = acc[3][mt][nt][i0 + 1] + bo2.y;

                float f0 = sigf(zf0),   f1 = sigf(zf1);
                float iv0 = sigf(zi0),  iv1 = sigf(zi1);
                float g0 = tanhf(zc0),  g1 = tanhf(zc1);
                float o0 = sigf(zo0),   o1 = sigf(zo1);

                float cn0 = cpv.x * f0 + iv0 * g0;
                float cn1 = cpv.y * f1 + iv1 * g1;
                float h0 = o0 * tanhf(cn0);
                float h1 = o1 * tanhf(cn1);

                *(float2*)(out_h + base) = make_float2(h0, h1);
                *(float2*)(out_c + base) = make_float2(cn0, cn1);
            }
        }
    }
}

extern "C" void kernel_launch(void* const* d_in, const int* in_sizes, int n_in,
                              void* d_out, int out_size) {
    // order: x, h_prev, c_prev, embedding_vec, Wf, Wi, Wc, Wo, bf, bi, bc, bo
    const float* x  = (const float*)d_in[0];
    const float* hp = (const float*)d_in[1];
    const float* cp = (const float*)d_in[2];
    const float* Wf = (const float*)d_in[4];
    const float* Wi = (const float*)d_in[5];
    const float* Wc = (const float*)d_in[6];
    const float* Wo = (const float*)d_in[7];
    const float* bf = (const float*)d_in[8];
    const float* bi = (const float*)d_in[9];
    const float* bc = (const float*)d_in[10];
    const float* bo = (const float*)d_in[11];

    float* out_h = (float*)d_out;
    float* out_c = out_h + (size_t)BATCH * HID;

    packA_kernel<<<dim3(BATCH / BM, NKB), 256>>>(x, hp);
    packB_kernel<<<dim3(HID / BNG, NKB), 256>>>(Wf, Wi, Wc, Wo);

    cudaFuncSetAttribute(lstm_mm_kernel,
                         cudaFuncAttributeMaxDynamicSharedMemorySize, SMEM_BYTES);
    dim3 grid(BATCH / BM, HID / BNG);   // (64, 32)
    lstm_mm_kernel<<<grid, 256, SMEM_BYTES>>>(cp, bf, bi, bc, bo, out_h, out_c);
}

// round 15
// speedup vs baseline: 1.8514x; 1.0610x over previous
#include <cuda_runtime.h>
#include <cstdint>
#include <cstddef>

#define BATCH   8192
#define HID     2048
#define KTOT    4096
#define BM      128
#define BNG     64              // per-gate cols per CTA (4 gates -> 256)
#define NKB     (KTOT / 16)     // 256 packed 16-k units
#define NKB64   (KTOT / 64)     // 64 mainloop stages
#define A_BLK   2048            // floats per packed A unit (128x16)
#define B_BLK   4096            // floats per packed B unit (16x256)
#define UNIT    (A_BLK + B_BLK) // 6144 floats = 24KB
#define NSTAGE  2
#define STG_FLT (4 * UNIT)      // 96KB per stage (four 16-k units)
#define SMEM_BYTES (NSTAGE * STG_FLT * 4)   // 192KB

__device__ __align__(16) float ABUF[(size_t)BATCH * KTOT];
__device__ __align__(16) float WBUF[(size_t)KTOT * 4 * HID];

__device__ __forceinline__ uint32_t s2u(const void* p) {
    uint32_t a;
    asm("{.reg .u64 t; cvta.to.shared.u64 t, %1; cvt.u32.u64 %0, t;}" : "=r"(a) : "l"(p));
    return a;
}

__device__ __forceinline__ float f2tf32f(float f) {
    uint32_t r;
    asm("cvt.rna.tf32.f32 %0, %1;" : "=r"(r) : "f"(f));
    return __uint_as_float(r);
}

__device__ __forceinline__ void cpa16(uint32_t dst, const float4* src) {
    asm volatile("cp.async.cg.shared.global [%0], [%1], 16;" :: "r"(dst), "l"(src));
}

__device__ __forceinline__ float sigf(float z) { return 1.0f / (1.0f + expf(-z)); }

__device__ __forceinline__ void mma_tf32(float c[4],
                                         uint32_t a0, uint32_t a1, uint32_t a2, uint32_t a3,
                                         uint32_t b0, uint32_t b1) {
    asm volatile(
        "mma.sync.aligned.m16n8k8.row.col.f32.tf32.tf32.f32 "
        "{%0,%1,%2,%3}, {%4,%5,%6,%7}, {%8,%9}, {%0,%1,%2,%3};"
        : "+f"(c[0]), "+f"(c[1]), "+f"(c[2]), "+f"(c[3])
        : "r"(a0), "r"(a1), "r"(a2), "r"(a3), "r"(b0), "r"(b1));
}

// ---------------- prepass: pack A (x||h) into fragment order ----------------
__global__ __launch_bounds__(256)
void packA_kernel(const float* __restrict__ x, const float* __restrict__ hp) {
    __shared__ float st[A_BLK];
    const int mblk = blockIdx.x, kb = blockIdx.y, tid = threadIdx.x;
    #pragma unroll
    for (int j = 0; j < 8; j++) {
        int fl = tid + 256 * j;
        int row = fl >> 4, k = fl & 15;
        int gk = kb * 16 + k;
        const float* src = (gk < 2048) ? x : hp;
        int kk2 = (gk < 2048) ? gk : gk - 2048;
        st[fl] = src[(size_t)(mblk * 128 + row) * 2048 + kk2];
    }
    __syncthreads();
    float* dst = ABUF + (size_t)(mblk * NKB + kb) * A_BLK;
    #pragma unroll
    for (int j = 0; j < 8; j++) {
        int d = tid + 256 * j;
        int w = d & 3, l = (d >> 2) & 31, mt = (d >> 7) & 3, wm = (d >> 9) & 1, kk = (d >> 10) & 1;
        int row = wm * 64 + mt * 16 + (l >> 2) + (w & 1) * 8;
        int k   = kk * 8 + (l & 3) + (w >> 1) * 4;
        dst[d] = f2tf32f(st[row * 16 + k]);
    }
}

// ---------------- prepass: pack W (4 gates) into fragment order ----------------
__global__ __launch_bounds__(256)
void packB_kernel(const float* __restrict__ Wf, const float* __restrict__ Wi,
                  const float* __restrict__ Wc, const float* __restrict__ Wo) {
    __shared__ float st[B_BLK];   // [g][16][64]
    const int nblk = blockIdx.x, kb = blockIdx.y, tid = threadIdx.x;
    const float* Wg[4] = {Wf, Wi, Wc, Wo};
    #pragma unroll
    for (int g = 0; g < 4; g++) {
        #pragma unroll
        for (int j = 0; j < 4; j++) {
            int fl = tid + 256 * j;
            int krow = fl >> 6, col = fl & 63;
            st[g * 1024 + fl] = Wg[g][(size_t)(kb * 16 + krow) * HID + nblk * 64 + col];
        }
    }
    __syncthreads();
    float* dst = WBUF + (size_t)(nblk * NKB + kb) * B_BLK;
    #pragma unroll
    for (int j = 0; j < 16; j++) {
        int d = tid + 256 * j;
        int w = d & 1, l = (d >> 1) & 31, nt = (d >> 6) & 1, g = (d >> 7) & 3,
            wn = (d >> 9) & 3, kk = (d >> 11) & 1;
        int k   = kk * 8 + (l & 3) + w * 4;
        int col = wn * 16 + nt * 8 + (l >> 2);
        dst[d] = f2tf32f(st[g * 1024 + k * 64 + col]);
    }
}

// ---------------- main GEMM + fused LSTM ----------------
__global__ __launch_bounds__(256, 1)
void lstm_mm_kernel(const float* __restrict__ cp,
                    const float* __restrict__ bf, const float* __restrict__ bi,
                    const float* __restrict__ bc, const float* __restrict__ bo,
                    float* __restrict__ out_h, float* __restrict__ out_c)
{
    extern __shared__ float sm[];
    const int tid    = threadIdx.x;
    const int lane   = tid & 31;
    const int wid    = tid >> 5;
    const int warp_m = wid & 1;   // 64 rows
    const int warp_n = wid >> 1;  // 16 cols per gate

    const int mblk = blockIdx.x;
    const int nblk = blockIdx.y;

    const float4* Ag = (const float4*)(ABUF + (size_t)mblk * NKB * A_BLK);
    const float4* Bg = (const float4*)(WBUF + (size_t)nblk * NKB * B_BLK);
    const uint32_t smb = s2u(sm);

    float acc[4][4][2][4];
    #pragma unroll
    for (int g = 0; g < 4; g++)
        #pragma unroll
        for (int mt = 0; mt < 4; mt++)
            #pragma unroll
            for (int nt = 0; nt < 2; nt++)
                #pragma unroll
                for (int r = 0; r < 4; r++)
                    acc[g][mt][nt][r] = 0.0f;

    // issue one 64-k stage = four consecutive 16-k packed units
    auto issue = [&](int kb64) {
        const int s = kb64 & (NSTAGE - 1);
        #pragma unroll
        for (int u = 0; u < 4; u++) {
            const int kb16 = kb64 * 4 + u;
            const uint32_t da = smb + (uint32_t)((s * STG_FLT + u * UNIT) * 4)
                                + (uint32_t)tid * 16;
            const float4* srcA = Ag + (size_t)kb16 * (A_BLK / 4) + tid;
            cpa16(da, srcA);
            cpa16(da + 256 * 16, srcA + 256);
            const uint32_t db = da + A_BLK * 4;
            const float4* srcB = Bg + (size_t)kb16 * (B_BLK / 4) + tid;
            #pragma unroll
            for (int j = 0; j < 4; j++)
                cpa16(db + (uint32_t)(j * 256 * 16), srcB + j * 256);
        }
    };

    auto ldfrag = [&](const float* stage, int sl, float4 af[4], float2 bfr[8]) {
        const float* Ab = stage + (sl >> 1) * UNIT;
        const float* Bb = Ab + A_BLK;
        const int kk = sl & 1;
        #pragma unroll
        for (int mt = 0; mt < 4; mt++)
            af[mt] = *(const float4*)&Ab[(((kk * 2 + warp_m) * 4 + mt) * 32 + lane) * 4];
        #pragma unroll
        for (int g = 0; g < 4; g++)
            #pragma unroll
            for (int nt = 0; nt < 2; nt++)
                bfr[g * 2 + nt] = *(const float2*)
                    &Bb[(((((kk * 4 + warp_n) * 4 + g) * 2 + nt)) * 32 + lane) * 2];
    };

    auto domma = [&](const float4 af[4], const float2 bfr[8]) {
        #pragma unroll
        for (int g = 0; g < 4; g++) {
            #pragma unroll
            for (int nt = 0; nt < 2; nt++) {
                const uint32_t b0 = __float_as_uint(bfr[g * 2 + nt].x);
                const uint32_t b1 = __float_as_uint(bfr[g * 2 + nt].y);
                #pragma unroll
                for (int mt = 0; mt < 4; mt++)
                    mma_tf32(acc[g][mt][nt],
                             __float_as_uint(af[mt].x), __float_as_uint(af[mt].y),
                             __float_as_uint(af[mt].z), __float_as_uint(af[mt].w),
                             b0, b1);
            }
        }
    };

    // prologue: stage 0 in flight (prefetch distance 1)
    issue(0);
    asm volatile("cp.async.commit_group;");

    float4 afr[2][4];
    float2 bfr2[2][8];

    for (int kb = 0; kb < NKB64; kb++) {
        // stage kb was issued one iteration ago; it had a full compute period to land
        asm volatile("cp.async.wait_group 0;");
        __syncthreads();
        // buffer (kb+1)&1 was last read in iteration kb-1; all readers passed the
        // barrier above, so refilling it now is safe (NSTAGE=2, distance=1).
        if (kb + 1 < NKB64) {
            issue(kb + 1);
            asm volatile("cp.async.commit_group;");
        }

        const float* stage = sm + (kb & (NSTAGE - 1)) * STG_FLT;
        ldfrag(stage, 0, afr[0], bfr2[0]);
        int cur = 0;
        #pragma unroll
        for (int sl = 0; sl < 8; sl++) {
            const int nxt = cur ^ 1;
            if (sl < 7) ldfrag(stage, sl + 1, afr[nxt], bfr2[nxt]);
            domma(afr[cur], bfr2[cur]);
            cur = nxt;
        }
    }

    // ---- fused LSTM epilogue ----
    const int m0 = mblk * BM;
    const int n0 = nblk * BNG;
    #pragma unroll
    for (int nt = 0; nt < 2; nt++) {
        const int col = n0 + warp_n * 16 + nt * 8 + (lane & 3) * 2;
        float2 bf2 = *(const float2*)(bf + col);
        float2 bi2 = *(const float2*)(bi + col);
        float2 bc2 = *(const float2*)(bc + col);
        float2 bo2 = *(const float2*)(bo + col);
        #pragma unroll
        for (int mt = 0; mt < 4; mt++) {
            #pragma unroll
            for (int half = 0; half < 2; half++) {
                const int m = m0 + warp_m * 64 + mt * 16 + (lane >> 2) + half * 8;
                const size_t base = (size_t)m * HID + col;
                float2 cpv = *(const float2*)(cp + base);
                const int i0 = half * 2;
                float zf0 = acc[0][mt][nt][i0]     + bf2.x;
                float zf1 = acc[0][mt][nt][i0 + 1] + bf2.y;
                float zi0 = acc[1][mt][nt][i0]     + bi2.x;
                float zi1 = acc[1][mt][nt][i0 + 1] + bi2.y;
                float zc0 = acc[2][mt][nt][i0]     + bc2.x;
                float zc1 = acc[2][mt][nt][i0 + 1] + bc2.y;
                float zo0 = acc[3][mt][nt][i0]     + bo2.x;
                float zo1 = acc[3][mt][nt][i0 + 1] + bo2.y;

                float f0 = sigf(zf0),   f1 = sigf(zf1);
                float iv0 = sigf(zi0),  iv1 = sigf(zi1);
                float g0 = tanhf(zc0),  g1 = tanhf(zc1);
                float o0 = sigf(zo0),   o1 = sigf(zo1);

                float cn0 = cpv.x * f0 + iv0 * g0;
                float cn1 = cpv.y * f1 + iv1 * g1;
                float h0 = o0 * tanhf(cn0);
                float h1 = o1 * tanhf(cn1);

                *(float2*)(out_h + base) = make_float2(h0, h1);
                *(float2*)(out_c + base) = make_float2(cn0, cn1);
            }
        }
    }
}

extern "C" void kernel_launch(void* const* d_in, const int* in_sizes, int n_in,
                              void* d_out, int out_size) {
    // order: x, h_prev, c_prev, embedding_vec, Wf, Wi, Wc, Wo, bf, bi, bc, bo
    const float* x  = (const float*)d_in[0];
    const float* hp = (const float*)d_in[1];
    const float* cp = (const float*)d_in[2];
    const float* Wf = (const float*)d_in[4];
    const float* Wi = (const float*)d_in[5];
    const float* Wc = (const float*)d_in[6];
    const float* Wo = (const float*)d_in[7];
    const float* bf = (const float*)d_in[8];
    const float* bi = (const float*)d_in[9];
    const float* bc = (const float*)d_in[10];
    const float* bo = (const float*)d_in[11];

    float* out_h = (float*)d_out;
    float* out_c = out_h + (size_t)BATCH * HID;

    packA_kernel<<<dim3(BATCH / BM, NKB), 256>>>(x, hp);
    packB_kernel<<<dim3(HID / BNG, NKB), 256>>>(Wf, Wi, Wc, Wo);

    cudaFuncSetAttribute(lstm_mm_kernel,
                         cudaFuncAttributeMaxDynamicSharedMemorySize, SMEM_BYTES);
    dim3 grid(BATCH / BM, HID / BNG);   // (64, 32)
    lstm_mm_kernel<<<grid, 256, SMEM_BYTES>>>(cp, bf, bi, bc, bo, out_h, out_c);
}